// round 5
// baseline (speedup 1.0000x reference)
#include <cuda_runtime.h>
#include <math.h>

#define BSZ      256                 // batch rows (bs)
#define DIM      128                 // feature dim
#define QK       131072              // queue size
#define ONEK     (QK + 1)            // 131073 columns of out
#define OUT_ELEMS (256LL * 131073LL) // 33,554,688
#define PROBS_OFF (OUT_ELEMS)
#define NEWMEM_OFF (OUT_ELEMS + 1)
#define BATCH    64
#define INV_T    (1.0f / 0.07f)

#define BMT 128
#define BNT 128
#define LDS_STRIDE 132               // pad: avoids same-bank stride-128 conflicts, keeps float4 align
#define SMEM_BYTES ((2 * BMT * LDS_STRIDE + BMT) * (int)sizeof(float))

__device__ float g_expPos[BSZ];
__device__ float g_rowsum[BSZ];
__device__ float g_scale;

// ---------------- packed f32x2 helpers (sm_103a FFMA2 path) ----------------
__device__ __forceinline__ unsigned long long pack2(float lo, float hi) {
    unsigned long long p;
    asm("mov.b64 %0, {%1, %2};" : "=l"(p) : "f"(lo), "f"(hi));
    return p;
}
__device__ __forceinline__ unsigned long long fma2(unsigned long long a,
                                                   unsigned long long b,
                                                   unsigned long long c) {
    unsigned long long d;
    asm("fma.rn.f32x2 %0, %1, %2, %3;" : "=l"(d) : "l"(a), "l"(b), "l"(c));
    return d;
}

// ---------------- kernel 1: l_pos, out[:,0], k_mean scatter ----------------
__global__ void k_init(const float* __restrict__ q, const float* __restrict__ k,
                       float* __restrict__ out) {
    int b = threadIdx.x;                 // 0..255
    int vid = b & 63;
    int own = b >> 6;

    const float* qr = q + b * DIM;
    float lpos = 0.f;
    #pragma unroll
    for (int c = 0; c < 4; ++c) {
        if (c == own) continue;
        const float* kr = k + (vid + 64 * c) * DIM;
        float d = 0.f;
        #pragma unroll 8
        for (int t = 0; t < DIM; ++t) d = fmaf(kr[t], qr[t], d);
        lpos += d;
    }
    lpos *= (1.0f / 3.0f);
    float e = __expf(lpos * INV_T);
    g_expPos[b] = e;
    g_rowsum[b] = e;                     // fresh each launch (graph-replay safe)
    out[(long long)b * ONEK] = e;        // unscaled; scale pass divides by Z

    // memory-bank update rows 0..63: mean of the 4 clips of each video
    for (int idx = b; idx < BATCH * DIM; idx += BSZ) {
        int v = idx >> 7, d = idx & 127;
        float m = 0.25f * (k[v * DIM + d] + k[(v + 64) * DIM + d] +
                           k[(v + 128) * DIM + d] + k[(v + 192) * DIM + d]);
        out[NEWMEM_OFF + (long long)v * DIM + d] = m;
    }
}

// ---------------- kernel 2: GEMM + exp epilogue + rowsum reduce ----------------
__global__ void __launch_bounds__(256, 1)
k_gemm(const float* __restrict__ q, const float* __restrict__ mem,
       float* __restrict__ out) {
    extern __shared__ float sm[];
    float* As = sm;                          // [128][132]
    float* Bs = sm + BMT * LDS_STRIDE;       // [128][132]
    float* rowsumS = Bs + BNT * LDS_STRIDE;  // [128]

    int tid = threadIdx.x;
    int n0 = blockIdx.x * BNT;
    int row0 = blockIdx.y * BMT;

    if (tid < BMT) rowsumS[tid] = 0.f;

    // Load A (q tile) and B (memory tile), float4 coalesced, natural [row][k] layout
    {
        const float4* srcA = (const float4*)(q + (long long)row0 * DIM);
        for (int idx = tid; idx < BMT * 32; idx += 256) {
            int m = idx >> 5, c = idx & 31;
            *(float4*)&As[m * LDS_STRIDE + 4 * c] = srcA[m * 32 + c];
        }
        const float4* srcB = (const float4*)(mem + (long long)n0 * DIM);
        for (int idx = tid; idx < BNT * 32; idx += 256) {
            int n = idx >> 5, c = idx & 31;
            *(float4*)&Bs[n * LDS_STRIDE + 4 * c] = srcB[n * 32 + c];
        }
    }
    __syncthreads();

    // thread (tm, tn) owns rows {tm + 16i} x cols {tn + 16j}  (strided -> bank friendly,
    // and 16 lanes write consecutive out addresses)
    int tn = tid & 15;
    int tm = tid >> 4;

    unsigned long long acc[8][4];            // [row i][col-pair j2]: lo=col tn+32*j2, hi=+16
    #pragma unroll
    for (int i = 0; i < 8; ++i)
        #pragma unroll
        for (int j = 0; j < 4; ++j) acc[i][j] = 0ull;

    #pragma unroll 2
    for (int k4 = 0; k4 < DIM / 4; ++k4) {
        float4 a4[8], b4[8];
        #pragma unroll
        for (int i = 0; i < 8; ++i)
            a4[i] = *(const float4*)(As + (tm + 16 * i) * LDS_STRIDE + 4 * k4);
        #pragma unroll
        for (int j = 0; j < 8; ++j)
            b4[j] = *(const float4*)(Bs + (tn + 16 * j) * LDS_STRIDE + 4 * k4);
        const float* af = (const float*)a4;
        const float* bf = (const float*)b4;
        #pragma unroll
        for (int t = 0; t < 4; ++t) {
            unsigned long long a2[8], b2[4];
            #pragma unroll
            for (int i = 0; i < 8; ++i) {
                float av = af[4 * i + t];
                a2[i] = pack2(av, av);
            }
            #pragma unroll
            for (int j = 0; j < 4; ++j)
                b2[j] = pack2(bf[4 * (2 * j) + t], bf[4 * (2 * j + 1) + t]);
            #pragma unroll
            for (int i = 0; i < 8; ++i)
                #pragma unroll
                for (int j = 0; j < 4; ++j)
                    acc[i][j] = fma2(a2[i], b2[j], acc[i][j]);
        }
    }

    // Epilogue: exp, store unscaled, accumulate row sums
    #pragma unroll
    for (int i = 0; i < 8; ++i) {
        int m = tm + 16 * i;
        long long rowoff = (long long)(row0 + m) * ONEK + 1 + n0;
        float rs = 0.f;
        #pragma unroll
        for (int j = 0; j < 4; ++j) {
            float lo = __uint_as_float((unsigned)(acc[i][j] & 0xffffffffu));
            float hi = __uint_as_float((unsigned)(acc[i][j] >> 32));
            float elo = __expf(lo * INV_T);
            float ehi = __expf(hi * INV_T);
            out[rowoff + tn + 32 * j]      = elo;
            out[rowoff + tn + 32 * j + 16] = ehi;
            rs += elo + ehi;
        }
        atomicAdd(&rowsumS[m], rs);
    }
    __syncthreads();
    if (tid < BMT) atomicAdd(&g_rowsum[row0 + tid], rowsumS[tid]);
}

// ---------------- kernel 3: Z, probs ----------------
__global__ void k_finalize(float* __restrict__ out) {
    __shared__ float sZ[BSZ], sP[BSZ];
    int b = threadIdx.x;
    float rs = g_rowsum[b];
    sZ[b] = rs;
    sP[b] = g_expPos[b] / rs;                // Z cancels in probs
    __syncthreads();
    for (int s = 128; s > 0; s >>= 1) {
        if (b < s) { sZ[b] += sZ[b + s]; sP[b] += sP[b + s]; }
        __syncthreads();
    }
    if (b == 0) {
        double Z = (double)sZ[0] / (double)(256.0 * 131073.0) * 1000000.0;
        g_scale = (float)(1.0 / Z);
        out[PROBS_OFF] = sP[0] * (1.0f / 256.0f);
    }
}

// ---------------- kernel 4: scale out by 1/Z (float4, bounds-checked tail) ----------------
#define SCALE_VEC4 (OUT_ELEMS / 4)           // 8,388,672 float4 (OUT_ELEMS divisible by 4)
__global__ void k_scale(float4* __restrict__ out) {
    float s = g_scale;
    long long i = (long long)blockIdx.x * blockDim.x + threadIdx.x;
    if (i >= SCALE_VEC4) return;             // grid is ceil-divided; guard the tail
    float4 v = out[i];
    v.x *= s; v.y *= s; v.z *= s; v.w *= s;
    out[i] = v;
}

extern "C" void kernel_launch(void* const* d_in, const int* in_sizes, int n_in,
                              void* d_out, int out_size) {
    const float* q   = (const float*)d_in[0];
    const float* k   = (const float*)d_in[1];
    const float* mem = (const float*)d_in[2];
    float* out = (float*)d_out;

    cudaFuncSetAttribute(k_gemm, cudaFuncAttributeMaxDynamicSharedMemorySize, SMEM_BYTES);

    // new_memory = memory (rows 0..63 overwritten by k_init afterwards)
    cudaMemcpyAsync(out + NEWMEM_OFF, mem, (size_t)QK * DIM * sizeof(float),
                    cudaMemcpyDeviceToDevice);

    k_init<<<1, BSZ>>>(q, k, out);
    k_gemm<<<dim3(QK / BNT, BSZ / BMT), 256, SMEM_BYTES>>>(q, mem, out);
    k_finalize<<<1, BSZ>>>(out);
    int scale_blocks = (int)((SCALE_VEC4 + 255) / 256);   // 32769: ceil, tail guarded
    k_scale<<<scale_blocks, 256>>>((float4*)out);
}

// round 10
// speedup vs baseline: 2.0470x; 2.0470x over previous
#include <cuda_runtime.h>
#include <cuda_bf16.h>
#include <stdint.h>
#include <math.h>

#define BSZ      256
#define DIM      128
#define QK       131072
#define ONEK     (QK + 1)
#define OUT_ELEMS (256LL * 131073LL)
#define PROBS_OFF  (OUT_ELEMS)
#define NEWMEM_OFF (OUT_ELEMS + 1)
#define BATCH    64
#define INV_T    (1.0f / 0.07f)

// ---- k_gemm smem layout: 4 bf16 tiles 128 rows x 272B (136 bf16, 128 used) ----
#define TS      272
#define SM_AH   0
#define SM_AL   (128 * TS)
#define SM_BH   (2 * 128 * TS)
#define SM_BL   (3 * 128 * TS)
#define SM_RS   (4 * 128 * TS)            // 128 floats rowsum
#define SMEM_TOTAL (4 * 128 * TS + 512)   // 139776 B

__device__ float g_expPos[BSZ];
__device__ float g_rowsum[BSZ];
__device__ float g_scale;

// ---------------- PTX helpers (all sm_80+ family-portable; NO tcgen05) ----------------
__device__ __forceinline__ uint32_t smem_u32(const void* p) {
    uint32_t a;
    asm("{ .reg .u64 t; cvta.to.shared.u64 t, %1; cvt.u32.u64 %0, t; }" : "=r"(a) : "l"(p));
    return a;
}
// pack two f32 -> bf16x2 (lower half = first arg)
__device__ __forceinline__ uint32_t cvt2(float lo, float hi) {
    uint32_t r;
    asm("cvt.rn.bf16x2.f32 %0, %1, %2;" : "=r"(r) : "f"(hi), "f"(lo));
    return r;
}
__device__ __forceinline__ float bf16_round(float x) {
    return __bfloat162float(__float2bfloat16_rn(x));
}
#define LDM4(r, addr) asm volatile( \
    "ldmatrix.sync.aligned.m8n8.x4.shared.b16 {%0,%1,%2,%3}, [%4];" \
    : "=r"((r)[0]), "=r"((r)[1]), "=r"((r)[2]), "=r"((r)[3]) : "r"(addr))
#define MMA(d, a, b0, b1) asm volatile( \
    "mma.sync.aligned.m16n8k16.row.col.f32.bf16.bf16.f32 " \
    "{%0,%1,%2,%3}, {%4,%5,%6,%7}, {%8,%9}, {%0,%1,%2,%3};" \
    : "+f"((d)[0]), "+f"((d)[1]), "+f"((d)[2]), "+f"((d)[3]) \
    : "r"((a)[0]), "r"((a)[1]), "r"((a)[2]), "r"((a)[3]), "r"(b0), "r"(b1))

// ---------------- kernel 1: l_pos, out[:,0], k_mean scatter ----------------
__global__ void k_init(const float* __restrict__ q, const float* __restrict__ k,
                       float* __restrict__ out) {
    int b = threadIdx.x;
    int vid = b & 63;
    int own = b >> 6;
    const float* qr = q + b * DIM;
    float lpos = 0.f;
    #pragma unroll
    for (int c = 0; c < 4; ++c) {
        if (c == own) continue;
        const float* kr = k + (vid + 64 * c) * DIM;
        float d = 0.f;
        #pragma unroll 8
        for (int t = 0; t < DIM; ++t) d = fmaf(kr[t], qr[t], d);
        lpos += d;
    }
    lpos *= (1.0f / 3.0f);
    float e = __expf(lpos * INV_T);
    g_expPos[b] = e;
    g_rowsum[b] = e;                       // fresh each launch (graph-replay safe)
    out[(long long)b * ONEK] = e;

    for (int idx = b; idx < BATCH * DIM; idx += BSZ) {
        int v = idx >> 7, d = idx & 127;
        float m = 0.25f * (k[v * DIM + d] + k[(v + 64) * DIM + d] +
                           k[(v + 128) * DIM + d] + k[(v + 192) * DIM + d]);
        out[NEWMEM_OFF + (long long)v * DIM + d] = m;
    }
}

// ---------------- kernel 2: split-bf16 HMMA GEMM + exp + rowsum ----------------
// grid (2, 1024): x = M-tile (inner: both M tiles reuse B tile via L2), y = N-chunk.
// 8 warps = 2 (M) x 4 (N); warp tile 64x32; mma m16n8k16, K=128 in 8 steps.
// D = Ah*Bh^T + Ah*Bl^T + Al*Bh^T  (lo*lo dropped, ~2^-18)
__global__ void __launch_bounds__(256, 1)
k_gemm(const float* __restrict__ q, const float* __restrict__ mem,
       float* __restrict__ out) {
    extern __shared__ char smem[];
    uint32_t sb = smem_u32(smem);
    int tid = threadIdx.x, wid = tid >> 5, lane = tid & 31;
    int wr = wid >> 2, wc = wid & 3;
    int row0 = blockIdx.x * 128;
    long long n0 = (long long)blockIdx.y * 128;

    if (tid < 128) ((float*)(smem + SM_RS))[tid] = 0.f;

    // --- convert f32 -> bf16 hi/lo into padded smem tiles (row stride 272B) ---
    {
        const float* srcs[2] = { q + (long long)row0 * DIM, mem + n0 * DIM };
        const int hoffs[2] = { SM_AH, SM_BH };
        const int loffs[2] = { SM_AL, SM_BL };
        #pragma unroll
        for (int t2 = 0; t2 < 2; ++t2) {
            const float* src = srcs[t2];
            #pragma unroll
            for (int it = 0; it < 8; ++it) {
                int e = tid + 256 * it;               // 0..2047: (row, 8-col group)
                int r = e >> 4, g = e & 15;
                const float4* s4 = (const float4*)(src + r * 128 + g * 8);
                float4 u = s4[0], v = s4[1];
                float xs[8] = {u.x, u.y, u.z, u.w, v.x, v.y, v.z, v.w};
                uint32_t hi[4], lo[4];
                #pragma unroll
                for (int j = 0; j < 4; ++j) {
                    float a = xs[2 * j], b = xs[2 * j + 1];
                    hi[j] = cvt2(a, b);
                    lo[j] = cvt2(a - bf16_round(a), b - bf16_round(b));
                }
                int off = r * TS + g * 16;
                *(uint4*)(smem + hoffs[t2] + off) = make_uint4(hi[0], hi[1], hi[2], hi[3]);
                *(uint4*)(smem + loffs[t2] + off) = make_uint4(lo[0], lo[1], lo[2], lo[3]);
            }
        }
    }
    __syncthreads();

    // per-thread ldmatrix base addresses
    // A x4: mat0 rows m0..7@k0, mat1 rows m0+8..15@k0, mat2 rows..@k+8, mat3 ..+8@k+8
    uint32_t aBase = sb + (uint32_t)(wr * 64 + (lane & 15)) * TS + (uint32_t)(lane >> 4) * 16;
    // B x4 (two n8 tiles): t0-7 rows n..n+7@k0, t8-15 same rows@k8, t16-23 rows+8@k0, t24-31 rows+8@k8
    uint32_t bRow = (uint32_t)(wc * 32 + ((lane >> 4) << 3) + (lane & 7));
    uint32_t bBase = sb + bRow * TS + (uint32_t)((lane >> 3) & 1) * 16;

    float acc[4][4][4];
    #pragma unroll
    for (int i = 0; i < 4; ++i)
        #pragma unroll
        for (int j = 0; j < 4; ++j)
            #pragma unroll
            for (int c = 0; c < 4; ++c) acc[i][j][c] = 0.f;

    #pragma unroll
    for (int ks = 0; ks < 8; ++ks) {
        uint32_t koff = ks * 32;              // 16 bf16 per k-step
        uint32_t ah[4][4], al[4][4], bh[8], bl[8];
        #pragma unroll
        for (int i = 0; i < 4; ++i) {
            LDM4(ah[i], aBase + SM_AH + i * (16 * TS) + koff);
            LDM4(al[i], aBase + SM_AL + i * (16 * TS) + koff);
        }
        LDM4(&bh[0], bBase + SM_BH + koff);
        LDM4(&bh[4], bBase + SM_BH + 16 * TS + koff);
        LDM4(&bl[0], bBase + SM_BL + koff);
        LDM4(&bl[4], bBase + SM_BL + 16 * TS + koff);
        #pragma unroll
        for (int i = 0; i < 4; ++i)
            #pragma unroll
            for (int j = 0; j < 4; ++j) {
                MMA(acc[i][j], ah[i], bh[2 * j], bh[2 * j + 1]);
                MMA(acc[i][j], ah[i], bl[2 * j], bl[2 * j + 1]);
                MMA(acc[i][j], al[i], bh[2 * j], bh[2 * j + 1]);
            }
    }

    // --- epilogue: exp, store, rowsums ---
    float* rowsum = (float*)(smem + SM_RS);
    int tq = lane >> 2, tp = lane & 3;
    #pragma unroll
    for (int i = 0; i < 4; ++i) {
        int mlo = wr * 64 + i * 16 + tq;       // local row (and mlo+8)
        float rlo = 0.f, rhi = 0.f;
        long long baseLo = (long long)(row0 + mlo) * ONEK + 1 + n0 + wc * 32 + 2 * tp;
        long long baseHi = baseLo + 8LL * ONEK;
        #pragma unroll
        for (int j = 0; j < 4; ++j) {
            float e0 = __expf(acc[i][j][0] * INV_T);
            float e1 = __expf(acc[i][j][1] * INV_T);
            float e2 = __expf(acc[i][j][2] * INV_T);
            float e3 = __expf(acc[i][j][3] * INV_T);
            out[baseLo + j * 8]     = e0;
            out[baseLo + j * 8 + 1] = e1;
            out[baseHi + j * 8]     = e2;
            out[baseHi + j * 8 + 1] = e3;
            rlo += e0 + e1;
            rhi += e2 + e3;
        }
        atomicAdd(&rowsum[mlo], rlo);
        atomicAdd(&rowsum[mlo + 8], rhi);
    }
    __syncthreads();
    if (tid < 128) atomicAdd(&g_rowsum[row0 + tid], rowsum[tid]);
}

// ---------------- kernel 3: Z, probs ----------------
__global__ void k_finalize(float* __restrict__ out) {
    __shared__ float sZ[BSZ], sP[BSZ];
    int b = threadIdx.x;
    float rsv = g_rowsum[b];
    sZ[b] = rsv;
    sP[b] = g_expPos[b] / rsv;             // Z cancels in probs
    __syncthreads();
    for (int s = 128; s > 0; s >>= 1) {
        if (b < s) { sZ[b] += sZ[b + s]; sP[b] += sP[b + s]; }
        __syncthreads();
    }
    if (b == 0) {
        double Z = (double)sZ[0] / (double)(256.0 * 131073.0) * 1000000.0;
        g_scale = (float)(1.0 / Z);
        out[PROBS_OFF] = sP[0] * (1.0f / 256.0f);
    }
}

// ---------------- kernel 4: scale out by 1/Z ----------------
#define SCALE_VEC4 (OUT_ELEMS / 4)
__global__ void k_scale(float4* __restrict__ out) {
    float s = g_scale;
    long long i = (long long)blockIdx.x * blockDim.x + threadIdx.x;
    if (i >= SCALE_VEC4) return;
    float4 v = out[i];
    v.x *= s; v.y *= s; v.z *= s; v.w *= s;
    out[i] = v;
}

extern "C" void kernel_launch(void* const* d_in, const int* in_sizes, int n_in,
                              void* d_out, int out_size) {
    const float* q   = (const float*)d_in[0];
    const float* k   = (const float*)d_in[1];
    const float* mem = (const float*)d_in[2];
    float* out = (float*)d_out;

    cudaFuncSetAttribute(k_gemm, cudaFuncAttributeMaxDynamicSharedMemorySize, SMEM_TOTAL);

    // new_memory = memory (rows 0..63 overwritten by k_init)
    cudaMemcpyAsync(out + NEWMEM_OFF, mem, (size_t)QK * DIM * sizeof(float),
                    cudaMemcpyDeviceToDevice);

    k_init<<<1, BSZ>>>(q, k, out);
    k_gemm<<<dim3(2, QK / 128), 256, SMEM_TOTAL>>>(q, mem, out);
    k_finalize<<<1, BSZ>>>(out);
    int scale_blocks = (int)((SCALE_VEC4 + 255) / 256);
    k_scale<<<scale_blocks, 256>>>((float4*)out);
}

// round 13
// speedup vs baseline: 2.1312x; 1.0411x over previous
#include <cuda_runtime.h>
#include <cuda_bf16.h>
#include <stdint.h>
#include <math.h>

#define BSZ      256
#define DIM      128
#define QK       131072
#define ONEK     (QK + 1)
#define OUT_ELEMS (256LL * 131073LL)
#define PROBS_OFF  (OUT_ELEMS)
#define NEWMEM_OFF (OUT_ELEMS + 1)
#define BATCH    64
#define INV_T    (1.0f / 0.07f)

// ---- k_gemm smem: A hi/lo 128x272B, B hi/lo 64x272B, rowsum ----
#define TS      272
#define SM_AH   0
#define SM_AL   (128 * TS)                 // 34816
#define SM_BH   (2 * 128 * TS)             // 69632
#define SM_BL   (SM_BH + 64 * TS)          // 87040
#define SM_RS   (SM_BL + 64 * TS)          // 104448 (128 floats)
#define SMEM_TOTAL (SM_RS + 512)           // 104960 B -> 2 CTAs/SM

__device__ float g_expPos[BSZ];
__device__ float g_rowsum[BSZ];            // zero-init; re-zeroed by k_finalize
__device__ float g_scale;
// Pre-converted A (q) hi/lo: 256 rows x 64 uint32 (bf16x2), 64KB each
__device__ __align__(16) uint32_t gAh[BSZ * 64];
__device__ __align__(16) uint32_t gAl[BSZ * 64];

// ---------------- PTX helpers (sm_80+ family-portable) ----------------
__device__ __forceinline__ uint32_t smem_u32(const void* p) {
    uint32_t a;
    asm("{ .reg .u64 t; cvta.to.shared.u64 t, %1; cvt.u32.u64 %0, t; }" : "=r"(a) : "l"(p));
    return a;
}
__device__ __forceinline__ unsigned long long to_global(const void* p) {
    unsigned long long g;
    asm("cvta.to.global.u64 %0, %1;" : "=l"(g) : "l"(p));
    return g;
}
__device__ __forceinline__ uint32_t cvt2(float lo, float hi) {   // lower half = first arg
    uint32_t r;
    asm("cvt.rn.bf16x2.f32 %0, %1, %2;" : "=r"(r) : "f"(hi), "f"(lo));
    return r;
}
__device__ __forceinline__ float bf16_round(float x) {
    return __bfloat162float(__float2bfloat16_rn(x));
}
#define CP_ASYNC16(saddr, gaddr) asm volatile( \
    "cp.async.ca.shared.global [%0], [%1], 16;" :: "r"(saddr), "l"(gaddr))
#define CP_COMMIT() asm volatile("cp.async.commit_group;" ::: "memory")
#define CP_WAIT0()  asm volatile("cp.async.wait_group 0;" ::: "memory")
#define LDM4(r, addr) asm volatile( \
    "ldmatrix.sync.aligned.m8n8.x4.shared.b16 {%0,%1,%2,%3}, [%4];" \
    : "=r"((r)[0]), "=r"((r)[1]), "=r"((r)[2]), "=r"((r)[3]) : "r"(addr))
#define MMA(d, a, b0, b1) asm volatile( \
    "mma.sync.aligned.m16n8k16.row.col.f32.bf16.bf16.f32 " \
    "{%0,%1,%2,%3}, {%4,%5,%6,%7}, {%8,%9}, {%0,%1,%2,%3};" \
    : "+f"((d)[0]), "+f"((d)[1]), "+f"((d)[2]), "+f"((d)[3]) \
    : "r"((a)[0]), "r"((a)[1]), "r"((a)[2]), "r"((a)[3]), "r"(b0), "r"(b1))

// ---------------- kernel 1: l_pos, out[:,0], k_mean scatter, A conversion ----------------
__global__ void k_init(const float* __restrict__ q, const float* __restrict__ k,
                       float* __restrict__ out) {
    int b = threadIdx.x;                   // 0..255
    int vid = b & 63;
    int own = b >> 6;
    const float* qr = q + b * DIM;
    float lpos = 0.f;
    #pragma unroll
    for (int c = 0; c < 4; ++c) {
        if (c == own) continue;
        const float* kr = k + (vid + 64 * c) * DIM;
        float d = 0.f;
        #pragma unroll 8
        for (int t = 0; t < DIM; ++t) d = fmaf(kr[t], qr[t], d);
        lpos += d;
    }
    lpos *= (1.0f / 3.0f);
    float e = __expf(lpos * INV_T);
    g_expPos[b] = e;
    out[(long long)b * ONEK] = e;          // unscaled; scale pass divides by Z

    // memory-bank update rows 0..63
    for (int idx = b; idx < BATCH * DIM; idx += BSZ) {
        int v = idx >> 7, d = idx & 127;
        float m = 0.25f * (k[v * DIM + d] + k[(v + 64) * DIM + d] +
                           k[(v + 128) * DIM + d] + k[(v + 192) * DIM + d]);
        out[NEWMEM_OFF + (long long)v * DIM + d] = m;
    }

    // convert q row b -> bf16 hi/lo packed (done ONCE, not per gemm CTA)
    {
        uint4* dh = (uint4*)gAh + b * 16;
        uint4* dl = (uint4*)gAl + b * 16;
        #pragma unroll
        for (int g = 0; g < 16; ++g) {
            const float4* s4 = (const float4*)(qr + g * 8);
            float4 u = s4[0], v = s4[1];
            float xs[8] = {u.x, u.y, u.z, u.w, v.x, v.y, v.z, v.w};
            uint32_t hi[4], lo[4];
            #pragma unroll
            for (int j = 0; j < 4; ++j) {
                float a = xs[2 * j], c = xs[2 * j + 1];
                hi[j] = cvt2(a, c);
                lo[j] = cvt2(a - bf16_round(a), c - bf16_round(c));
            }
            dh[g] = make_uint4(hi[0], hi[1], hi[2], hi[3]);
            dl[g] = make_uint4(lo[0], lo[1], lo[2], lo[3]);
        }
    }
}

// ---------------- kernel 2: split-bf16 HMMA GEMM + exp + rowsum ----------------
// grid (2, 2048): x = M-tile of 128 (inner -> B tile L2 reuse), y = N-chunk of 64.
// 8 warps = 2 (M) x 4 (N); warp tile 64x16; D = Ah*Bh + Ah*Bl + Al*Bh.
__global__ void __launch_bounds__(256, 2)
k_gemm(const float* __restrict__ q, const float* __restrict__ mem,
       float* __restrict__ out) {
    extern __shared__ char smem[];
    uint32_t sb = smem_u32(smem);
    int tid = threadIdx.x, wid = tid >> 5, lane = tid & 31;
    int wr = wid >> 2, wc = wid & 3;
    int row0 = blockIdx.x * 128;
    long long n0 = (long long)blockIdx.y * 64;

    if (tid < 128) ((float*)(smem + SM_RS))[tid] = 0.f;

    // --- A tiles: cp.async copy of pre-converted bf16 (no math) ---
    {
        unsigned long long srcH = to_global((uint4*)gAh + (long long)row0 * 16);
        unsigned long long srcL = to_global((uint4*)gAl + (long long)row0 * 16);
        #pragma unroll
        for (int it = 0; it < 8; ++it) {
            int i = tid + 256 * it;                 // 0..2047
            int r = i >> 4, g = i & 15;
            uint32_t doff = (uint32_t)(r * TS + g * 16);
            CP_ASYNC16(sb + SM_AH + doff, srcH + (unsigned long long)i * 16);
            CP_ASYNC16(sb + SM_AL + doff, srcL + (unsigned long long)i * 16);
        }
        CP_COMMIT();
    }

    // --- B tile: convert f32 -> bf16 hi/lo (64 rows x 128 cols) ---
    #pragma unroll
    for (int it = 0; it < 4; ++it) {
        int e = tid + 256 * it;                     // 0..1023
        int r = e >> 4, g = e & 15;
        const float4* s4 = (const float4*)(mem + (n0 + r) * 128 + g * 8);
        float4 u = s4[0], v = s4[1];
        float xs[8] = {u.x, u.y, u.z, u.w, v.x, v.y, v.z, v.w};
        uint32_t hi[4], lo[4];
        #pragma unroll
        for (int j = 0; j < 4; ++j) {
            float a = xs[2 * j], c = xs[2 * j + 1];
            hi[j] = cvt2(a, c);
            lo[j] = cvt2(a - bf16_round(a), c - bf16_round(c));
        }
        int off = r * TS + g * 16;
        *(uint4*)(smem + SM_BH + off) = make_uint4(hi[0], hi[1], hi[2], hi[3]);
        *(uint4*)(smem + SM_BL + off) = make_uint4(lo[0], lo[1], lo[2], lo[3]);
    }
    CP_WAIT0();
    __syncthreads();

    // ldmatrix bases
    // A x4: rows (wr*64 + lane&15), +16B for lanes 16..31 -> mats {m0-7@k0, m8-15@k0, m0-7@k8, m8-15@k8}
    uint32_t aBase = sb + (uint32_t)((wr * 64 + (lane & 15)) * TS) + (uint32_t)((lane >> 4) * 16);
    // B x4: rows wc*16 + 8*((lane>>4)&1) + (lane&7), +16B by ((lane>>3)&1)
    //   -> mats {n0-7@k0, n0-7@k8, n8-15@k0, n8-15@k8}; tile j pair = (r[2j], r[2j+1])
    uint32_t bBase = sb + (uint32_t)((wc * 16 + ((lane >> 4) << 3) + (lane & 7)) * TS)
                        + (uint32_t)(((lane >> 3) & 1) * 16);

    float acc[4][2][4];
    #pragma unroll
    for (int i = 0; i < 4; ++i)
        #pragma unroll
        for (int j = 0; j < 2; ++j)
            #pragma unroll
            for (int c = 0; c < 4; ++c) acc[i][j][c] = 0.f;

    #pragma unroll
    for (int ks = 0; ks < 8; ++ks) {
        uint32_t koff = ks * 32;
        uint32_t ah[4][4], al[4][4], bh[4], bl[4];
        #pragma unroll
        for (int i = 0; i < 4; ++i) {
            LDM4(ah[i], aBase + SM_AH + i * (16 * TS) + koff);
            LDM4(al[i], aBase + SM_AL + i * (16 * TS) + koff);
        }
        LDM4(bh, bBase + SM_BH + koff);
        LDM4(bl, bBase + SM_BL + koff);
        #pragma unroll
        for (int i = 0; i < 4; ++i)
            #pragma unroll
            for (int j = 0; j < 2; ++j) {
                MMA(acc[i][j], ah[i], bh[2 * j], bh[2 * j + 1]);
                MMA(acc[i][j], ah[i], bl[2 * j], bl[2 * j + 1]);
                MMA(acc[i][j], al[i], bh[2 * j], bh[2 * j + 1]);
            }
    }

    // --- epilogue: exp, store, rowsums ---
    float* rowsum = (float*)(smem + SM_RS);
    int tq = lane >> 2, tp = lane & 3;
    #pragma unroll
    for (int i = 0; i < 4; ++i) {
        int mlo = wr * 64 + i * 16 + tq;
        float rlo = 0.f, rhi = 0.f;
        long long baseLo = (long long)(row0 + mlo) * ONEK + 1 + n0 + wc * 16 + 2 * tp;
        long long baseHi = baseLo + 8LL * ONEK;
        #pragma unroll
        for (int j = 0; j < 2; ++j) {
            float e0 = __expf(acc[i][j][0] * INV_T);
            float e1 = __expf(acc[i][j][1] * INV_T);
            float e2 = __expf(acc[i][j][2] * INV_T);
            float e3 = __expf(acc[i][j][3] * INV_T);
            out[baseLo + j * 8]     = e0;
            out[baseLo + j * 8 + 1] = e1;
            out[baseHi + j * 8]     = e2;
            out[baseHi + j * 8 + 1] = e3;
            rlo += e0 + e1;
            rhi += e2 + e3;
        }
        atomicAdd(&rowsum[mlo], rlo);
        atomicAdd(&rowsum[mlo + 8], rhi);
    }
    __syncthreads();
    if (tid < 128) atomicAdd(&g_rowsum[row0 + tid], rowsum[tid]);
}

// ---------------- kernel 3: Z, probs (re-zeroes g_rowsum for next replay) ----------------
__global__ void k_finalize(float* __restrict__ out) {
    __shared__ float sZ[BSZ], sP[BSZ];
    int b = threadIdx.x;
    float rsv = g_rowsum[b] + g_expPos[b];   // rowsum incl. l_pos column
    g_rowsum[b] = 0.f;                       // restore invariant for next launch
    sZ[b] = rsv;
    sP[b] = g_expPos[b] / rsv;               // Z cancels in probs
    __syncthreads();
    for (int s = 128; s > 0; s >>= 1) {
        if (b < s) { sZ[b] += sZ[b + s]; sP[b] += sP[b + s]; }
        __syncthreads();
    }
    if (b == 0) {
        double Z = (double)sZ[0] / (double)(256.0 * 131073.0) * 1000000.0;
        g_scale = (float)(1.0 / Z);
        out[PROBS_OFF] = sP[0] * (1.0f / 256.0f);
    }
}

// ---------------- kernel 4: scale out by 1/Z (streaming) ----------------
#define SCALE_VEC4 (OUT_ELEMS / 4)
__global__ void k_scale(float4* __restrict__ out) {
    float s = g_scale;
    long long i = (long long)blockIdx.x * blockDim.x + threadIdx.x;
    if (i >= SCALE_VEC4) return;
    float4 v = __ldcs(&out[i]);
    v.x *= s; v.y *= s; v.z *= s; v.w *= s;
    __stcs(&out[i], v);
}

extern "C" void kernel_launch(void* const* d_in, const int* in_sizes, int n_in,
                              void* d_out, int out_size) {
    const float* q   = (const float*)d_in[0];
    const float* k   = (const float*)d_in[1];
    const float* mem = (const float*)d_in[2];
    float* out = (float*)d_out;

    cudaFuncSetAttribute(k_gemm, cudaFuncAttributeMaxDynamicSharedMemorySize, SMEM_TOTAL);

    // new_memory = memory (rows 0..63 overwritten by k_init)
    cudaMemcpyAsync(out + NEWMEM_OFF, mem, (size_t)QK * DIM * sizeof(float),
                    cudaMemcpyDeviceToDevice);

    k_init<<<1, BSZ>>>(q, k, out);
    k_gemm<<<dim3(2, QK / 64), 256, SMEM_TOTAL>>>(q, mem, out);
    k_finalize<<<1, BSZ>>>(out);
    int scale_blocks = (int)((SCALE_VEC4 + 255) / 256);
    k_scale<<<scale_blocks, 256>>>((float4*)out);
}